// round 1
// baseline (speedup 1.0000x reference)
#include <cuda_runtime.h>

// Collapsed chain scratch: C^T stored as [10][784], plus folded bias [10].
__device__ float g_M[10 * 784];
__device__ float g_c[10];

// Layer dims of the chain
#define NLAYERS 9
__constant__ int c_din[NLAYERS]  = {784, 69, 31, 10, 10, 10, 10, 10, 10};
__constant__ int c_dout[NLAYERS] = {69, 31, 10, 10, 10, 10, 10, 10, 10};

// ---------------------------------------------------------------------------
// Kernel 1: compose the 9 linear layers into a single 784x10 matrix + bias.
// Thread i < 784 computes row i of the composed matrix C (i.e. starts from
// column i of W0 and pushes it through W1..W8). Thread 784 folds the biases.
// ---------------------------------------------------------------------------
__global__ void compose_kernel(
    const float* __restrict__ W0, const float* __restrict__ b0,
    const float* __restrict__ W1, const float* __restrict__ b1,
    const float* __restrict__ W2, const float* __restrict__ b2,
    const float* __restrict__ W3, const float* __restrict__ b3,
    const float* __restrict__ W4, const float* __restrict__ b4,
    const float* __restrict__ W5, const float* __restrict__ b5,
    const float* __restrict__ W6, const float* __restrict__ b6,
    const float* __restrict__ W7, const float* __restrict__ b7,
    const float* __restrict__ W8, const float* __restrict__ b8)
{
    const float* Ws[NLAYERS] = {W0, W1, W2, W3, W4, W5, W6, W7, W8};
    const float* bs[NLAYERS] = {b0, b1, b2, b3, b4, b5, b6, b7, b8};

    int i = blockIdx.x * blockDim.x + threadIdx.x;

    if (i < 784) {
        // Row i of C: a = W0[:, i] (length 69), then propagate through W1..W8.
        float a[69];
        float t[69];
        for (int j = 0; j < 69; j++) a[j] = W0[j * 784 + i];
        int cur = 69;
        for (int l = 1; l < NLAYERS; l++) {
            int din = c_din[l], dout = c_dout[l];
            const float* W = Ws[l];
            for (int j = 0; j < dout; j++) {
                float s = 0.0f;
                for (int k = 0; k < din; k++) s += a[k] * W[j * din + k];
                t[j] = s;
            }
            for (int j = 0; j < dout; j++) a[j] = t[j];
            cur = dout;
        }
        // Store transposed: g_M[j][i]
        for (int j = 0; j < 10; j++) g_M[j * 784 + i] = a[j];
        (void)cur;
    } else if (i == 784) {
        // Fold biases: c = b0; c = c @ Wl^T + bl for l = 1..8
        float cvec[69];
        float t[69];
        for (int j = 0; j < 69; j++) cvec[j] = b0[j];
        for (int l = 1; l < NLAYERS; l++) {
            int din = c_din[l], dout = c_dout[l];
            const float* W = Ws[l];
            const float* b = bs[l];
            for (int j = 0; j < dout; j++) {
                float s = b[j];
                for (int k = 0; k < din; k++) s += cvec[k] * W[j * din + k];
                t[j] = s;
            }
            for (int j = 0; j < dout; j++) cvec[j] = t[j];
        }
        for (int j = 0; j < 10; j++) g_c[j] = cvec[j];
    }
}

// ---------------------------------------------------------------------------
// Kernel 2: y[rows,10] = x[rows,784] @ C[784,10] + c
// C^T ([10][784]) staged into shared memory (broadcast LDS.128 per warp).
// One thread per row, float4 loads of x.
// ---------------------------------------------------------------------------
__global__ void __launch_bounds__(256) fused_gemm_kernel(
    const float* __restrict__ x, float* __restrict__ y, int rows)
{
    __shared__ float Ms[10 * 784];
    __shared__ float cs[10];

    // Stage composed matrix into shared (7840 floats = 1960 float4)
    {
        const float4* src = reinterpret_cast<const float4*>(g_M);
        float4* dst = reinterpret_cast<float4*>(Ms);
        for (int t = threadIdx.x; t < (10 * 784) / 4; t += blockDim.x)
            dst[t] = src[t];
        if (threadIdx.x < 10) cs[threadIdx.x] = g_c[threadIdx.x];
    }
    __syncthreads();

    int row = blockIdx.x * blockDim.x + threadIdx.x;
    if (row >= rows) return;

    const float4* xr = reinterpret_cast<const float4*>(x + (size_t)row * 784);

    float acc[10];
#pragma unroll
    for (int j = 0; j < 10; j++) acc[j] = cs[j];

#pragma unroll 4
    for (int k4 = 0; k4 < 196; k4++) {
        float4 v = xr[k4];
#pragma unroll
        for (int j = 0; j < 10; j++) {
            float4 m = reinterpret_cast<const float4*>(Ms + j * 784)[k4];
            acc[j] += v.x * m.x + v.y * m.y + v.z * m.z + v.w * m.w;
        }
    }

    float* yr = y + (size_t)row * 10;
#pragma unroll
    for (int j = 0; j < 10; j++) yr[j] = acc[j];
}

// ---------------------------------------------------------------------------
extern "C" void kernel_launch(void* const* d_in, const int* in_sizes, int n_in,
                              void* d_out, int out_size)
{
    const float* x = (const float*)d_in[0];
    const float* W[NLAYERS];
    const float* b[NLAYERS];
    for (int l = 0; l < NLAYERS; l++) {
        W[l] = (const float*)d_in[1 + 2 * l];
        b[l] = (const float*)d_in[2 + 2 * l];
    }
    float* y = (float*)d_out;

    int rows = in_sizes[0] / 784;

    // Kernel 1: compose (785 lanes of work)
    compose_kernel<<<4, 256>>>(
        W[0], b[0], W[1], b[1], W[2], b[2], W[3], b[3], W[4], b[4],
        W[5], b[5], W[6], b[6], W[7], b[7], W[8], b[8]);

    // Kernel 2: fused GEMM
    int threads = 256;
    int blocks = (rows + threads - 1) / threads;
    fused_gemm_kernel<<<blocks, threads>>>(x, y, rows);
}

// round 2
// speedup vs baseline: 1.9775x; 1.9775x over previous
#include <cuda_runtime.h>

// Collapsed chain: A = W8*...*W0 (10x784) stored row-major in g_M, bias in g_c.
__device__ float g_M[10 * 784];
__device__ float g_c[10];
__device__ float g_P[10 * 69];   // P = W8*...*W1

// ---------------- packed f32x2 helpers ----------------
__device__ __forceinline__ unsigned long long pk2(float a, float b) {
    unsigned long long r;
    asm("mov.b64 %0, {%1, %2};" : "=l"(r) : "f"(a), "f"(b));
    return r;
}
__device__ __forceinline__ void fma2(unsigned long long& d, unsigned long long a, unsigned long long b) {
    asm("fma.rn.f32x2 %0, %1, %2, %0;" : "+l"(d) : "l"(a), "l"(b));
}
__device__ __forceinline__ float hsum2(unsigned long long v) {
    float lo, hi;
    asm("mov.b64 {%0, %1}, %2;" : "=f"(lo), "=f"(hi) : "l"(v));
    return lo + hi;
}

// ---------------------------------------------------------------------------
// Stage 1: P = W8*W7*...*W1 (10x69) and folded bias c (10). One block.
// All intermediates in shared memory; fully parallel over elements.
// ---------------------------------------------------------------------------
__global__ void compose_small(
    const float* __restrict__ b0,
    const float* __restrict__ W1, const float* __restrict__ b1,
    const float* __restrict__ W2, const float* __restrict__ b2,
    const float* __restrict__ W3, const float* __restrict__ b3,
    const float* __restrict__ W4, const float* __restrict__ b4,
    const float* __restrict__ W5, const float* __restrict__ b5,
    const float* __restrict__ W6, const float* __restrict__ b6,
    const float* __restrict__ W7, const float* __restrict__ b7,
    const float* __restrict__ W8, const float* __restrict__ b8)
{
    __shared__ float A[690], B[690];
    __shared__ float v0[69], v1[69];
    const int tid = threadIdx.x;

    // P2 = W2 (10x31) * W1 (31x69)  -> [10][69]
    for (int e = tid; e < 690; e += blockDim.x) {
        int a = e / 69, b = e % 69;
        float s = 0.f;
        for (int m = 0; m < 31; m++) s += W2[a * 31 + m] * W1[m * 69 + b];
        A[e] = s;
    }
    __syncthreads();

    const float* Wl[6] = {W3, W4, W5, W6, W7, W8};
    const float* bl[6] = {b3, b4, b5, b6, b7, b8};
    float* cur = A; float* nxt = B;
    for (int l = 0; l < 6; l++) {
        const float* W = Wl[l];
        for (int e = tid; e < 690; e += blockDim.x) {
            int a = e / 69, b = e % 69;
            float s = 0.f;
            #pragma unroll
            for (int m = 0; m < 10; m++) s += W[a * 10 + m] * cur[m * 69 + b];
            nxt[e] = s;
        }
        __syncthreads();
        float* t = cur; cur = nxt; nxt = t;
    }
    for (int e = tid; e < 690; e += blockDim.x) g_P[e] = cur[e];

    // Bias fold: c0 = b0; c_l = W_l * c_{l-1} + b_l
    if (tid < 69) v0[tid] = b0[tid];
    __syncthreads();
    if (tid < 31) {
        float s = b1[tid];
        for (int k = 0; k < 69; k++) s += W1[tid * 69 + k] * v0[k];
        v1[tid] = s;
    }
    __syncthreads();
    if (tid < 10) {
        float s = b2[tid];
        for (int k = 0; k < 31; k++) s += W2[tid * 31 + k] * v1[k];
        v0[tid] = s;
    }
    __syncthreads();
    float* cv = v0; float* nv = v1;
    for (int l = 0; l < 6; l++) {
        if (tid < 10) {
            float s = bl[l][tid];
            #pragma unroll
            for (int k = 0; k < 10; k++) s += Wl[l][tid * 10 + k] * cv[k];
            nv[tid] = s;
        }
        __syncthreads();
        float* t = cv; cv = nv; nv = t;
    }
    if (tid < 10) g_c[tid] = cv[tid];
}

// ---------------------------------------------------------------------------
// Stage 2: g_M[j][i] = sum_k P[j][k] * W0[k][i]   (10x784 = 7840 elems)
// Coalesced over i; P broadcast from shared.
// ---------------------------------------------------------------------------
__global__ void compose_big(const float* __restrict__ W0)
{
    __shared__ float Ps[690];
    for (int e = threadIdx.x; e < 690; e += blockDim.x) Ps[e] = g_P[e];
    __syncthreads();

    int idx = blockIdx.x * blockDim.x + threadIdx.x;
    if (idx >= 7840) return;
    int j = idx / 784, i = idx % 784;
    float s = 0.f;
    #pragma unroll 23
    for (int k = 0; k < 69; k++) s += Ps[j * 69 + k] * W0[k * 784 + i];
    g_M[idx] = s;
}

// ---------------------------------------------------------------------------
// GEMM: y[rows,10] = x[rows,784] @ A^T + c
// Warp layout: 4 lanes per row (k-quarters), each lane-group handles 2 rows.
// 16 rows/warp, 128 rows/block. Packed f32x2 FMA.
// ---------------------------------------------------------------------------
__global__ void __launch_bounds__(256) gemm_kernel(
    const float* __restrict__ x, float* __restrict__ y, int rows)
{
    __shared__ float Ms[10 * 784];
    __shared__ float cs[10];
    for (int t = threadIdx.x; t < 1960; t += 256)
        reinterpret_cast<float4*>(Ms)[t] = reinterpret_cast<const float4*>(g_M)[t];
    if (threadIdx.x < 10) cs[threadIdx.x] = g_c[threadIdx.x];
    __syncthreads();

    const int warp = threadIdx.x >> 5;
    const int lane = threadIdx.x & 31;
    const int s = lane & 3;      // k-quarter: float4 index 4t+s
    const int r = lane >> 2;     // 0..7 : row pair within warp

    const long baseA = (long)blockIdx.x * 128 + warp * 16 + r * 2;
    const long baseB = baseA + 1;
    const bool okA = baseA < rows;
    const bool okB = baseB < rows;

    const float4* xa = reinterpret_cast<const float4*>(x + (okA ? baseA : 0) * 784) + s;
    const float4* xb = reinterpret_cast<const float4*>(x + (okB ? baseB : 0) * 784) + s;
    const float4* mbase = reinterpret_cast<const float4*>(Ms) + s;

    unsigned long long accA[10], accB[10];
    #pragma unroll
    for (int j = 0; j < 10; j++) { accA[j] = 0ULL; accB[j] = 0ULL; }

    #pragma unroll 2
    for (int t = 0; t < 49; t++) {
        float4 va = xa[t * 4];
        float4 vb = xb[t * 4];
        unsigned long long a01 = pk2(va.x, va.y), a23 = pk2(va.z, va.w);
        unsigned long long b01 = pk2(vb.x, vb.y), b23 = pk2(vb.z, vb.w);
        const float4* m = mbase + t * 4;
        #pragma unroll
        for (int j = 0; j < 10; j++) {
            float4 mv = m[j * 196];
            unsigned long long m01 = pk2(mv.x, mv.y), m23 = pk2(mv.z, mv.w);
            fma2(accA[j], a01, m01);
            fma2(accA[j], a23, m23);
            fma2(accB[j], b01, m01);
            fma2(accB[j], b23, m23);
        }
    }

    // Reduce over the 4 k-quarter lanes (xor 1, xor 2), then add bias.
    float outA[10], outB[10];
    #pragma unroll
    for (int j = 0; j < 10; j++) {
        float vA = hsum2(accA[j]);
        float vB = hsum2(accB[j]);
        vA += __shfl_xor_sync(0xffffffffu, vA, 1);
        vA += __shfl_xor_sync(0xffffffffu, vA, 2);
        vB += __shfl_xor_sync(0xffffffffu, vB, 1);
        vB += __shfl_xor_sync(0xffffffffu, vB, 2);
        outA[j] = vA + cs[j];
        outB[j] = vB + cs[j];
    }

    if (s == 0) {
        if (okA) {
            float2* ya = reinterpret_cast<float2*>(y + baseA * 10);
            #pragma unroll
            for (int j = 0; j < 5; j++) ya[j] = make_float2(outA[2 * j], outA[2 * j + 1]);
        }
        if (okB) {
            float2* yb = reinterpret_cast<float2*>(y + baseB * 10);
            #pragma unroll
            for (int j = 0; j < 5; j++) yb[j] = make_float2(outB[2 * j], outB[2 * j + 1]);
        }
    }
}

// ---------------------------------------------------------------------------
extern "C" void kernel_launch(void* const* d_in, const int* in_sizes, int n_in,
                              void* d_out, int out_size)
{
    const float* x = (const float*)d_in[0];
    const float* W[9];
    const float* b[9];
    for (int l = 0; l < 9; l++) {
        W[l] = (const float*)d_in[1 + 2 * l];
        b[l] = (const float*)d_in[2 + 2 * l];
    }
    float* y = (float*)d_out;
    int rows = in_sizes[0] / 784;

    compose_small<<<1, 256>>>(
        b[0],
        W[1], b[1], W[2], b[2], W[3], b[3], W[4], b[4],
        W[5], b[5], W[6], b[6], W[7], b[7], W[8], b[8]);
    compose_big<<<31, 256>>>(W[0]);

    int blocks = (rows + 127) / 128;
    gemm_kernel<<<blocks, 256>>>(x, y, rows);
}

// round 3
// speedup vs baseline: 2.3290x; 1.1777x over previous
#include <cuda_runtime.h>

// Collapsed chain: M = W8*...*W0 (10x784) row-major in g_M, folded bias g_c.
__device__ float g_M[10 * 784];
__device__ float g_c[10];
__device__ float g_P[10 * 69];   // P = W8*...*W1

// ---------------- packed f32x2 helpers ----------------
__device__ __forceinline__ unsigned long long pk2(float a, float b) {
    unsigned long long r;
    asm("mov.b64 %0, {%1, %2};" : "=l"(r) : "f"(a), "f"(b));
    return r;
}
__device__ __forceinline__ void fma2(unsigned long long& d, unsigned long long a, unsigned long long b) {
    asm("fma.rn.f32x2 %0, %1, %2, %0;" : "+l"(d) : "l"(a), "l"(b));
}
__device__ __forceinline__ float hsum2(unsigned long long v) {
    float lo, hi;
    asm("mov.b64 {%0, %1}, %2;" : "=f"(lo), "=f"(hi) : "l"(v));
    return lo + hi;
}

// ---------------------------------------------------------------------------
// Stage 1: P = W8*...*W1 (10x69) and folded bias c (10). One block.
// ALL weights preloaded to shared in one parallel wave, then pure on-chip math.
// ---------------------------------------------------------------------------
__global__ void __launch_bounds__(256) compose_small(
    const float* __restrict__ b0,
    const float* __restrict__ W1, const float* __restrict__ b1,
    const float* __restrict__ W2, const float* __restrict__ b2,
    const float* __restrict__ W3, const float* __restrict__ b3,
    const float* __restrict__ W4, const float* __restrict__ b4,
    const float* __restrict__ W5, const float* __restrict__ b5,
    const float* __restrict__ W6, const float* __restrict__ b6,
    const float* __restrict__ W7, const float* __restrict__ b7,
    const float* __restrict__ W8, const float* __restrict__ b8)
{
    __shared__ float sW1[31 * 69];
    __shared__ float sW2[10 * 31];
    __shared__ float sWs[6][100];       // W3..W8
    __shared__ float sb0[69], sb1[31];
    __shared__ float sbs[7][10];        // b2..b8
    __shared__ float A[690], B[690];
    __shared__ float v0[69], v1[69];

    const int tid = threadIdx.x;
    const int nt = blockDim.x;

    // ---- parallel preload (one DRAM latency wave) ----
    for (int e = tid; e < 31 * 69; e += nt) sW1[e] = W1[e];
    for (int e = tid; e < 310; e += nt) sW2[e] = W2[e];
    {
        const float* Wg[6] = {W3, W4, W5, W6, W7, W8};
        for (int l = 0; l < 6; l++)
            if (tid < 100) sWs[l][tid] = Wg[l][tid];
    }
    if (tid < 69) sb0[tid] = b0[tid];
    if (tid < 31) sb1[tid] = b1[tid];
    {
        const float* bg[7] = {b2, b3, b4, b5, b6, b7, b8};
        for (int l = 0; l < 7; l++)
            if (tid < 10) sbs[l][tid] = bg[l][tid];
    }
    __syncthreads();

    // ---- P2 = W2 (10x31) * W1 (31x69) ----
    for (int e = tid; e < 690; e += nt) {
        int a = e / 69, b = e % 69;
        float s = 0.f;
        #pragma unroll 31
        for (int m = 0; m < 31; m++) s += sW2[a * 31 + m] * sW1[m * 69 + b];
        A[e] = s;
    }
    __syncthreads();

    // ---- fold W3..W8 ----
    float* cur = A; float* nxt = B;
    for (int l = 0; l < 6; l++) {
        for (int e = tid; e < 690; e += nt) {
            int a = e / 69, b = e % 69;
            float s = 0.f;
            #pragma unroll
            for (int m = 0; m < 10; m++) s += sWs[l][a * 10 + m] * cur[m * 69 + b];
            nxt[e] = s;
        }
        __syncthreads();
        float* t = cur; cur = nxt; nxt = t;
    }
    for (int e = tid; e < 690; e += nt) g_P[e] = cur[e];

    // ---- bias fold ----
    if (tid < 31) {
        float s = sb1[tid];
        #pragma unroll 23
        for (int k = 0; k < 69; k++) s += sW1[tid * 69 + k] * sb0[k];
        v1[tid] = s;
    }
    __syncthreads();
    if (tid < 10) {
        float s = sbs[0][tid];   // b2
        #pragma unroll 31
        for (int k = 0; k < 31; k++) s += sW2[tid * 31 + k] * v1[k];
        v0[tid] = s;
    }
    __syncthreads();
    float* cv = v0; float* nv = v1;
    for (int l = 0; l < 6; l++) {
        if (tid < 10) {
            float s = sbs[l + 1][tid];
            #pragma unroll
            for (int k = 0; k < 10; k++) s += sWs[l][tid * 10 + k] * cv[k];
            nv[tid] = s;
        }
        __syncthreads();
        float* t = cv; cv = nv; nv = t;
    }
    if (tid < 10) g_c[tid] = cv[tid];
}

// ---------------------------------------------------------------------------
// Stage 2: g_M[j][i] = sum_k P[j][k] * W0[k][i]  — float4 vectorized.
// Thread <-> (j, i4), i4 in [0,196). Coalesced W0 loads, full unroll for MLP.
// ---------------------------------------------------------------------------
__global__ void __launch_bounds__(256) compose_big(const float* __restrict__ W0)
{
    __shared__ float Ps[690];
    for (int e = threadIdx.x; e < 690; e += blockDim.x) Ps[e] = g_P[e];
    __syncthreads();

    int idx = blockIdx.x * blockDim.x + threadIdx.x;
    if (idx >= 1960) return;
    int j = idx / 196, i4 = idx % 196;

    const float4* W04 = reinterpret_cast<const float4*>(W0);
    float4 acc = make_float4(0.f, 0.f, 0.f, 0.f);
    #pragma unroll 23
    for (int k = 0; k < 69; k++) {
        float4 w = W04[k * 196 + i4];
        float p = Ps[j * 69 + k];
        acc.x += p * w.x; acc.y += p * w.y;
        acc.z += p * w.z; acc.w += p * w.w;
    }
    reinterpret_cast<float4*>(g_M)[idx] = acc;
}

// ---------------------------------------------------------------------------
// GEMM: y[rows,10] = x[rows,784] @ M^T + c
// Lane layout: s = lane&7 (k-octant, 8x16B = full 128B line per row),
//              r = lane>>3 (4 row slots). 8 rows per warp, 64 per block.
// Software-pipelined prefetch of next iteration's loads. Packed f32x2 FMA.
// ---------------------------------------------------------------------------
__global__ void __launch_bounds__(256) gemm_kernel(
    const float* __restrict__ x, float* __restrict__ y, int rows)
{
    __shared__ float Ms[10 * 784];
    __shared__ float cs[10];
    for (int t = threadIdx.x; t < 1960; t += 256)
        reinterpret_cast<float4*>(Ms)[t] = reinterpret_cast<const float4*>(g_M)[t];
    if (threadIdx.x < 10) cs[threadIdx.x] = g_c[threadIdx.x];
    __syncthreads();

    const int warp = threadIdx.x >> 5;
    const int lane = threadIdx.x & 31;
    const int s = lane & 7;      // k-octant: float4 index s + 8t
    const int r = lane >> 3;     // row slot 0..3

    const long rowA = (long)blockIdx.x * 64 + warp * 8 + r;
    const long rowB = rowA + 4;
    const bool okA = rowA < rows;
    const bool okB = rowB < rows;

    const float4* xa = reinterpret_cast<const float4*>(x + (okA ? rowA : 0) * 784);
    const float4* xb = reinterpret_cast<const float4*>(x + (okB ? rowB : 0) * 784);
    const float4* Ms4 = reinterpret_cast<const float4*>(Ms);

    unsigned long long accA[10], accB[10];
    #pragma unroll
    for (int j = 0; j < 10; j++) { accA[j] = 0ULL; accB[j] = 0ULL; }

    // main loop: t = 0..23 covers float4 idx s+8t (192 float4 = 768 floats)
    float4 va = xa[s];
    float4 vb = xb[s];
    #pragma unroll 2
    for (int t = 0; t < 24; t++) {
        float4 na, nb;
        if (t < 23) {
            na = xa[s + 8 * (t + 1)];
            nb = xb[s + 8 * (t + 1)];
        }
        unsigned long long a01 = pk2(va.x, va.y), a23 = pk2(va.z, va.w);
        unsigned long long b01 = pk2(vb.x, vb.y), b23 = pk2(vb.z, vb.w);
        const float4* m = Ms4 + s + 8 * t;
        #pragma unroll
        for (int j = 0; j < 10; j++) {
            float4 mv = m[j * 196];
            unsigned long long m01 = pk2(mv.x, mv.y), m23 = pk2(mv.z, mv.w);
            fma2(accA[j], a01, m01);
            fma2(accA[j], a23, m23);
            fma2(accB[j], b01, m01);
            fma2(accB[j], b23, m23);
        }
        va = na; vb = nb;
    }
    // tail: float4 idx 192..195 handled by lanes s<4
    if (s < 4) {
        float4 ta = xa[192 + s];
        float4 tb = xb[192 + s];
        unsigned long long a01 = pk2(ta.x, ta.y), a23 = pk2(ta.z, ta.w);
        unsigned long long b01 = pk2(tb.x, tb.y), b23 = pk2(tb.z, tb.w);
        #pragma unroll
        for (int j = 0; j < 10; j++) {
            float4 mv = Ms4[j * 196 + 192 + s];
            unsigned long long m01 = pk2(mv.x, mv.y), m23 = pk2(mv.z, mv.w);
            fma2(accA[j], a01, m01);
            fma2(accA[j], a23, m23);
            fma2(accB[j], b01, m01);
            fma2(accB[j], b23, m23);
        }
    }

    // reduce across the 8 k-octant lanes, add bias
    float outA[10], outB[10];
    #pragma unroll
    for (int j = 0; j < 10; j++) {
        float vA = hsum2(accA[j]);
        float vB = hsum2(accB[j]);
        vA += __shfl_xor_sync(0xffffffffu, vA, 1);
        vA += __shfl_xor_sync(0xffffffffu, vA, 2);
        vA += __shfl_xor_sync(0xffffffffu, vA, 4);
        vB += __shfl_xor_sync(0xffffffffu, vB, 1);
        vB += __shfl_xor_sync(0xffffffffu, vB, 2);
        vB += __shfl_xor_sync(0xffffffffu, vB, 4);
        outA[j] = vA + cs[j];
        outB[j] = vB + cs[j];
    }

    if (s == 0) {
        if (okA) {
            float2* ya = reinterpret_cast<float2*>(y + rowA * 10);
            #pragma unroll
            for (int j = 0; j < 5; j++) ya[j] = make_float2(outA[2 * j], outA[2 * j + 1]);
        }
        if (okB) {
            float2* yb = reinterpret_cast<float2*>(y + rowB * 10);
            #pragma unroll
            for (int j = 0; j < 5; j++) yb[j] = make_float2(outB[2 * j], outB[2 * j + 1]);
        }
    }
}

// ---------------------------------------------------------------------------
extern "C" void kernel_launch(void* const* d_in, const int* in_sizes, int n_in,
                              void* d_out, int out_size)
{
    const float* x = (const float*)d_in[0];
    const float* W[9];
    const float* b[9];
    for (int l = 0; l < 9; l++) {
        W[l] = (const float*)d_in[1 + 2 * l];
        b[l] = (const float*)d_in[2 + 2 * l];
    }
    float* y = (float*)d_out;
    int rows = in_sizes[0] / 784;

    compose_small<<<1, 256>>>(
        b[0],
        W[1], b[1], W[2], b[2], W[3], b[3], W[4], b[4],
        W[5], b[5], W[6], b[6], W[7], b[7], W[8], b[8]);
    compose_big<<<8, 256>>>(W[0]);

    int blocks = (rows + 63) / 64;
    gemm_kernel<<<blocks, 256>>>(x, y, rows);
}

// round 4
// speedup vs baseline: 3.5780x; 1.5363x over previous
#include <cuda_runtime.h>

// Collapsed chain: M = W8*...*W0 (10x784) row-major in g_M, folded bias g_c.
__device__ __align__(16) float g_M[10 * 784];
__device__ float g_c[10];

// ---------------- packed f32x2 helpers ----------------
__device__ __forceinline__ void fma2(unsigned long long& d, unsigned long long a, unsigned long long b) {
    asm("fma.rn.f32x2 %0, %1, %2, %0;" : "+l"(d) : "l"(a), "l"(b));
}
__device__ __forceinline__ float hsum2(unsigned long long v) {
    float lo, hi;
    asm("mov.b64 {%0, %1}, %2;" : "=f"(lo), "=f"(hi) : "l"(v));
    return lo + hi;
}

// ---------------------------------------------------------------------------
// Compose kernel (single launch, grid=8).
// Each block redundantly computes P = W8*...*W1 (10x69) with a *thread-local*
// register chain (70 threads: 69 matrix columns + 1 bias column, NO syncs
// inside the chain), then computes its slice of M = P * W0 (float4/coalesced).
// Block 0 also folds the final bias c = P*b0 + fold(b1..b8).
// ---------------------------------------------------------------------------
__global__ void __launch_bounds__(256) compose_kernel(
    const float* __restrict__ W0, const float* __restrict__ b0,
    const float* __restrict__ W1, const float* __restrict__ b1,
    const float* __restrict__ W2, const float* __restrict__ b2,
    const float* __restrict__ W3, const float* __restrict__ b3,
    const float* __restrict__ W4, const float* __restrict__ b4,
    const float* __restrict__ W5, const float* __restrict__ b5,
    const float* __restrict__ W6, const float* __restrict__ b6,
    const float* __restrict__ W7, const float* __restrict__ b7,
    const float* __restrict__ W8, const float* __restrict__ b8)
{
    __shared__ float sW2[10 * 31];
    __shared__ float sWs[6][100];     // W3..W8
    __shared__ float sb1[31];
    __shared__ float sbs[7][10];      // b2..b8
    __shared__ float sb0[69];
    __shared__ float sP[10 * 69];
    __shared__ float sc[10];          // fold(b1..b8) part

    const int tid = threadIdx.x;

    // ---- parallel preload of all small operands ----
    for (int e = tid; e < 310; e += 256) sW2[e] = W2[e];
    if (tid < 100) {
        sWs[0][tid] = W3[tid]; sWs[1][tid] = W4[tid]; sWs[2][tid] = W5[tid];
        sWs[3][tid] = W6[tid]; sWs[4][tid] = W7[tid]; sWs[5][tid] = W8[tid];
    }
    if (tid < 31) sb1[tid] = b1[tid];
    if (tid < 69) sb0[tid] = b0[tid];
    if (tid < 10) {
        sbs[0][tid] = b2[tid]; sbs[1][tid] = b3[tid]; sbs[2][tid] = b4[tid];
        sbs[3][tid] = b5[tid]; sbs[4][tid] = b6[tid]; sbs[5][tid] = b7[tid];
        sbs[6][tid] = b8[tid];
    }
    __syncthreads();

    // ---- thread-local chain: no syncs, all in registers ----
    if (tid < 70) {
        const bool isBias = (tid == 69);
        float a[31];
        if (!isBias) {
            #pragma unroll
            for (int m = 0; m < 31; m++) a[m] = W1[m * 69 + tid];  // coalesced
        } else {
            #pragma unroll
            for (int m = 0; m < 31; m++) a[m] = sb1[m];
        }
        // W2 stage: t = W2 @ a (+ b2 for bias column)
        float t[10];
        #pragma unroll
        for (int j = 0; j < 10; j++) {
            float s = isBias ? sbs[0][j] : 0.f;
            #pragma unroll
            for (int m = 0; m < 31; m++) s += sW2[j * 31 + m] * a[m];
            t[j] = s;
        }
        // W3..W8 stages
        #pragma unroll
        for (int l = 0; l < 6; l++) {
            float u[10];
            #pragma unroll
            for (int j = 0; j < 10; j++) {
                float s = isBias ? sbs[l + 1][j] : 0.f;
                #pragma unroll
                for (int m = 0; m < 10; m++) s += sWs[l][j * 10 + m] * t[m];
                u[j] = s;
            }
            #pragma unroll
            for (int j = 0; j < 10; j++) t[j] = u[j];
        }
        if (!isBias) {
            #pragma unroll
            for (int j = 0; j < 10; j++) sP[j * 69 + tid] = t[j];
        } else {
            #pragma unroll
            for (int j = 0; j < 10; j++) sc[j] = t[j];
        }
    }
    __syncthreads();

    // ---- M slice: idx in [0,1960) float4 outputs, 69-step dot ----
    int idx = blockIdx.x * 256 + tid;
    if (idx < 1960) {
        int j = idx / 196, i4 = idx % 196;
        const float4* W04 = reinterpret_cast<const float4*>(W0);
        float4 acc = make_float4(0.f, 0.f, 0.f, 0.f);
        #pragma unroll 23
        for (int k = 0; k < 69; k++) {
            float4 w = W04[k * 196 + i4];
            float p = sP[j * 69 + k];
            acc.x += p * w.x; acc.y += p * w.y;
            acc.z += p * w.z; acc.w += p * w.w;
        }
        reinterpret_cast<float4*>(g_M)[idx] = acc;
    }

    // ---- final bias: c = P @ b0 + fold(b1..b8) ----
    if (blockIdx.x == 0 && tid < 10) {
        float s = sc[tid];
        #pragma unroll 23
        for (int k = 0; k < 69; k++) s += sP[tid * 69 + k] * sb0[k];
        g_c[tid] = s;
    }
}

// ---------------------------------------------------------------------------
// GEMM: y[rows,10] = x[rows,784] @ M^T + c
// Lane layout: s = lane&7 (k-octant, warp covers full 128B line per row),
//              r = lane>>3 (4 row slots); 2 rows/thread -> 8 rows/warp.
// Depth-2 prefetch (4 LDG.128 in flight/thread). ulonglong2 loads feed
// fma.rn.f32x2 directly (no repack movs).
// ---------------------------------------------------------------------------
__global__ void __launch_bounds__(256, 2) gemm_kernel(
    const float* __restrict__ x, float* __restrict__ y, int rows)
{
    __shared__ __align__(16) float Ms[10 * 784];
    __shared__ float cs[10];
    for (int t = threadIdx.x; t < 1960; t += 256)
        reinterpret_cast<float4*>(Ms)[t] = reinterpret_cast<const float4*>(g_M)[t];
    if (threadIdx.x < 10) cs[threadIdx.x] = g_c[threadIdx.x];
    __syncthreads();

    const int warp = threadIdx.x >> 5;
    const int lane = threadIdx.x & 31;
    const int s = lane & 7;      // k-octant: 16B chunk index s + 8t
    const int r = lane >> 3;     // row slot 0..3

    const long rowA = (long)blockIdx.x * 64 + warp * 8 + r;
    const long rowB = rowA + 4;
    const bool okA = rowA < rows;
    const bool okB = rowB < rows;

    const ulonglong2* xa = reinterpret_cast<const ulonglong2*>(x + (okA ? rowA : 0) * 784);
    const ulonglong2* xb = reinterpret_cast<const ulonglong2*>(x + (okB ? rowB : 0) * 784);
    const ulonglong2* Ms2 = reinterpret_cast<const ulonglong2*>(Ms);

    unsigned long long accA[10], accB[10];
    #pragma unroll
    for (int j = 0; j < 10; j++) { accA[j] = 0ULL; accB[j] = 0ULL; }

    // depth-2 prefetch ring
    ulonglong2 pfa[2], pfb[2];
    pfa[0] = xa[s];      pfb[0] = xb[s];
    pfa[1] = xa[s + 8];  pfb[1] = xb[s + 8];

    #pragma unroll 4
    for (int t = 0; t < 24; t++) {
        ulonglong2 va = pfa[t & 1];
        ulonglong2 vb = pfb[t & 1];
        if (t < 22) {
            pfa[t & 1] = xa[s + 8 * (t + 2)];
            pfb[t & 1] = xb[s + 8 * (t + 2)];
        }
        const ulonglong2* m = Ms2 + s + 8 * t;
        #pragma unroll
        for (int j = 0; j < 10; j++) {
            ulonglong2 mv = m[j * 196];
            fma2(accA[j], va.x, mv.x);
            fma2(accA[j], va.y, mv.y);
            fma2(accB[j], vb.x, mv.x);
            fma2(accB[j], vb.y, mv.y);
        }
    }
    // tail: 16B chunks 192..195 handled by lanes s<4
    if (s < 4) {
        ulonglong2 ta = xa[192 + s];
        ulonglong2 tb = xb[192 + s];
        #pragma unroll
        for (int j = 0; j < 10; j++) {
            ulonglong2 mv = Ms2[j * 196 + 192 + s];
            fma2(accA[j], ta.x, mv.x);
            fma2(accA[j], ta.y, mv.y);
            fma2(accB[j], tb.x, mv.x);
            fma2(accB[j], tb.y, mv.y);
        }
    }

    // reduce across the 8 k-octant lanes, add bias
    float outA[10], outB[10];
    #pragma unroll
    for (int j = 0; j < 10; j++) {
        float vA = hsum2(accA[j]);
        float vB = hsum2(accB[j]);
        vA += __shfl_xor_sync(0xffffffffu, vA, 1);
        vA += __shfl_xor_sync(0xffffffffu, vA, 2);
        vA += __shfl_xor_sync(0xffffffffu, vA, 4);
        vB += __shfl_xor_sync(0xffffffffu, vB, 1);
        vB += __shfl_xor_sync(0xffffffffu, vB, 2);
        vB += __shfl_xor_sync(0xffffffffu, vB, 4);
        outA[j] = vA + cs[j];
        outB[j] = vB + cs[j];
    }

    if (s == 0) {
        if (okA) {
            float2* ya = reinterpret_cast<float2*>(y + rowA * 10);
            #pragma unroll
            for (int j = 0; j < 5; j++) ya[j] = make_float2(outA[2 * j], outA[2 * j + 1]);
        }
        if (okB) {
            float2* yb = reinterpret_cast<float2*>(y + rowB * 10);
            #pragma unroll
            for (int j = 0; j < 5; j++) yb[j] = make_float2(outB[2 * j], outB[2 * j + 1]);
        }
    }
}

// ---------------------------------------------------------------------------
extern "C" void kernel_launch(void* const* d_in, const int* in_sizes, int n_in,
                              void* d_out, int out_size)
{
    const float* x = (const float*)d_in[0];
    const float* W[9];
    const float* b[9];
    for (int l = 0; l < 9; l++) {
        W[l] = (const float*)d_in[1 + 2 * l];
        b[l] = (const float*)d_in[2 + 2 * l];
    }
    float* y = (float*)d_out;
    int rows = in_sizes[0] / 784;

    compose_kernel<<<8, 256>>>(
        W[0], b[0], W[1], b[1], W[2], b[2], W[3], b[3], W[4], b[4],
        W[5], b[5], W[6], b[6], W[7], b[7], W[8], b[8]);

    int blocks = (rows + 63) / 64;
    gemm_kernel<<<blocks, 256>>>(x, y, rows);
}